// round 12
// baseline (speedup 1.0000x reference)
#include <cuda_runtime.h>

// heightfield: [16,1,512,512] f32 -> same shape.
// out[w] = 1 - clip( max_{r=1..16}( pad(row)[w+r] - r/10 ) - row[w], 0, 1 )
// 8 outputs/thread (lowest mem-op density: 6 LDG.128 + 2 STG.128 per 8 out),
// thread-local bias g[k]=v[k]-0.1k, shared 9-wide core max + suffix/prefix
// fixups, warp-uniform pad path, evict-first streaming stores.

#define IM 512
#define NEG (-1e30f)
#define THREADS 256

__global__ __launch_bounds__(THREADS) void shadow_ov8cs(const float* __restrict__ in,
                                                        float* __restrict__ out) {
    const int gtid = blockIdx.x * THREADS + threadIdx.x;
    const int c0 = gtid << 3;              // element index, 8 per thread
    const int col = c0 & (IM - 1);         // column within row (0..504, step 8)

    const float* p = in + c0;

    float g[24];
    // Warp spans 256 aligned columns; only warps with col>=256 can reach pad.
    if (col < 256) {
        #pragma unroll
        for (int i = 0; i < 6; ++i) {
            float4 v = *reinterpret_cast<const float4*>(p + 4 * i);
            g[4*i+0] = v.x - 0.1f * (4*i+0);
            g[4*i+1] = v.y - 0.1f * (4*i+1);
            g[4*i+2] = v.z - 0.1f * (4*i+2);
            g[4*i+3] = v.w - 0.1f * (4*i+3);
        }
    } else {
        // quads 0,1 always in-row (col <= 504 -> col+7 <= 511)
        {
            float4 v = *reinterpret_cast<const float4*>(p);
            g[0] = v.x; g[1] = v.y - 0.1f; g[2] = v.z - 0.2f; g[3] = v.w - 0.3f;
            float4 u = *reinterpret_cast<const float4*>(p + 4);
            g[4] = u.x - 0.4f; g[5] = u.y - 0.5f; g[6] = u.z - 0.6f; g[7] = u.w - 0.7f;
        }
        #pragma unroll
        for (int i = 2; i < 6; ++i) {
            if (col + 4 * i <= IM - 4) {
                float4 v = *reinterpret_cast<const float4*>(p + 4 * i);
                g[4*i+0] = v.x - 0.1f * (4*i+0);
                g[4*i+1] = v.y - 0.1f * (4*i+1);
                g[4*i+2] = v.z - 0.1f * (4*i+2);
                g[4*i+3] = v.w - 0.1f * (4*i+3);
            } else {                       // beyond row end: never wins
                g[4*i+0] = NEG; g[4*i+1] = NEG; g[4*i+2] = NEG; g[4*i+3] = NEG;
            }
        }
    }

    // core: max over g[8..16] (tree), shared by all 8 windows [j+1, j+16]
    const float t89   = fmaxf(g[8],  g[9]);
    const float t1011 = fmaxf(g[10], g[11]);
    const float t1213 = fmaxf(g[12], g[13]);
    const float t1415 = fmaxf(g[14], g[15]);
    const float core  = fmaxf(fmaxf(fmaxf(t89, t1011), fmaxf(t1213, t1415)), g[16]);

    // suffix maxes over g[1..7]: suf[k] = max(g[k..7])
    float suf[8];
    suf[7] = g[7];
    #pragma unroll
    for (int k = 6; k >= 1; --k) suf[k] = fmaxf(g[k], suf[k + 1]);

    // prefix maxes over g[17..23]
    float pre[24];
    pre[17] = g[17];
    #pragma unroll
    for (int k = 18; k <= 23; ++k) pre[k] = fmaxf(pre[k - 1], g[k]);

    float m[8];
    m[0] = fmaxf(core, suf[1]);
    #pragma unroll
    for (int j = 1; j <= 6; ++j) m[j] = fmaxf(fmaxf(core, suf[j + 1]), pre[16 + j]);
    m[7] = fmaxf(core, pre[23]);

    float4 o0, o1;
    o0.x = __saturatef(1.0f + (g[0] - m[0]));
    o0.y = __saturatef(1.0f + (g[1] - m[1]));
    o0.z = __saturatef(1.0f + (g[2] - m[2]));
    o0.w = __saturatef(1.0f + (g[3] - m[3]));
    o1.x = __saturatef(1.0f + (g[4] - m[4]));
    o1.y = __saturatef(1.0f + (g[5] - m[5]));
    o1.z = __saturatef(1.0f + (g[6] - m[6]));
    o1.w = __saturatef(1.0f + (g[7] - m[7]));

    __stcs(reinterpret_cast<float4*>(out + c0), o0);
    __stcs(reinterpret_cast<float4*>(out + c0 + 4), o1);
}

extern "C" void kernel_launch(void* const* d_in, const int* in_sizes, int n_in,
                              void* d_out, int out_size) {
    const float* in = (const float*)d_in[0];
    float* out = (float*)d_out;
    const int n = in_sizes[0];                 // 4,194,304
    const int threads_total = n / 8;           // 524,288
    shadow_ov8cs<<<threads_total / THREADS, THREADS>>>(in, out);
}

// round 13
// speedup vs baseline: 1.2657x; 1.2657x over previous
#include <cuda_runtime.h>

// heightfield: [16,1,512,512] f32 -> same shape.
// out[w] = 1 - clip( max_{r=1..16}( pad(row)[w+r] - r/10 ) - row[w], 0, 1 )
// Best-wall configuration: 512-thread CTAs (grid 2048 -> lowest launch
// overhead measured), thread-local bias g[k]=v[k]-0.1k, 5 overlapped float4
// loads, warp-uniform pad path, balanced-tree max (dep depth 4), evict-first
// streaming stores.

#define IM 512
#define NEG (-1e30f)
#define THREADS 512

__global__ __launch_bounds__(THREADS, 4) void shadow_final(const float* __restrict__ in,
                                                           float* __restrict__ out) {
    const int gtid = blockIdx.x * THREADS + threadIdx.x;
    const int c0 = gtid << 2;              // element index (row-major)
    const int col = c0 & (IM - 1);         // column within row

    const float* p = in + c0;

    float g[20];
    // Warp spans 128 aligned columns; only wbase==384 warps can reach the pad.
    if (col < 384) {
        #pragma unroll
        for (int i = 0; i < 5; ++i) {
            float4 v = *reinterpret_cast<const float4*>(p + 4 * i);
            g[4*i+0] = v.x - 0.1f * (4*i+0);
            g[4*i+1] = v.y - 0.1f * (4*i+1);
            g[4*i+2] = v.z - 0.1f * (4*i+2);
            g[4*i+3] = v.w - 0.1f * (4*i+3);
        }
    } else {
        float4 v0 = *reinterpret_cast<const float4*>(p);
        g[0] = v0.x; g[1] = v0.y - 0.1f; g[2] = v0.z - 0.2f; g[3] = v0.w - 0.3f;
        #pragma unroll
        for (int i = 1; i < 5; ++i) {
            if (col + 4 * i <= IM - 4) {
                float4 v = *reinterpret_cast<const float4*>(p + 4 * i);
                g[4*i+0] = v.x - 0.1f * (4*i+0);
                g[4*i+1] = v.y - 0.1f * (4*i+1);
                g[4*i+2] = v.z - 0.1f * (4*i+2);
                g[4*i+3] = v.w - 0.1f * (4*i+3);
            } else {                       // beyond row end: never wins
                g[4*i+0] = NEG; g[4*i+1] = NEG; g[4*i+2] = NEG; g[4*i+3] = NEG;
            }
        }
    }

    // balanced-tree max over g[4..16] (13 values, dep depth 4)
    const float t45   = fmaxf(g[4],  g[5]);
    const float t67   = fmaxf(g[6],  g[7]);
    const float t89   = fmaxf(g[8],  g[9]);
    const float t1011 = fmaxf(g[10], g[11]);
    const float t1213 = fmaxf(g[12], g[13]);
    const float t1415 = fmaxf(g[14], g[15]);
    const float q0 = fmaxf(t45,  t67);
    const float q1 = fmaxf(t89,  t1011);
    const float q2 = fmaxf(t1213, t1415);
    const float cm = fmaxf(fmaxf(q0, q1), fmaxf(q2, g[16]));

    // window j: k in [j+1, j+16]
    const float a = fmaxf(g[2], g[3]);
    const float b = fmaxf(g[17], g[18]);
    const float m0 = fmaxf(cm, fmaxf(g[1], a));
    const float m1 = fmaxf(cm, fmaxf(a, g[17]));
    const float m2 = fmaxf(cm, fmaxf(g[3], b));
    const float m3 = fmaxf(cm, fmaxf(b, g[19]));

    float4 o;
    o.x = __saturatef(1.0f + (g[0] - m0));
    o.y = __saturatef(1.0f + (g[1] - m1));
    o.z = __saturatef(1.0f + (g[2] - m2));
    o.w = __saturatef(1.0f + (g[3] - m3));

    __stcs(reinterpret_cast<float4*>(out + c0), o);   // evict-first streaming store
}

extern "C" void kernel_launch(void* const* d_in, const int* in_sizes, int n_in,
                              void* d_out, int out_size) {
    const float* in = (const float*)d_in[0];
    float* out = (float*)d_out;
    const int n = in_sizes[0];                 // 4,194,304
    const int threads_total = n / 4;           // 1,048,576
    shadow_final<<<threads_total / THREADS, THREADS>>>(in, out);
}

// round 14
// speedup vs baseline: 1.2704x; 1.0037x over previous
#include <cuda_runtime.h>

// heightfield: [16,1,512,512] f32 -> same shape.
// out[w] = 1 - clip( max_{r=1..16}( pad(row)[w+r] - r/10 ) - row[w], 0, 1 )
// Dual independent chains: each thread processes the SAME column quad in two
// image halves (c0 and c0+HALF). 10 mutually-independent LDG.128 (MLP=10),
// two interleaved max trees, shared column/pad logic. stcs stores,
// warp-uniform fast path, 256-thread CTAs, grid 2048.

#define IM 512
#define NEG (-1e30f)
#define THREADS 256
#define HALF (4194304 / 2)             // element offset between the two tasks

__global__ __launch_bounds__(THREADS) void shadow_dual(const float* __restrict__ in,
                                                       float* __restrict__ out) {
    const int gtid = blockIdx.x * THREADS + threadIdx.x;
    const int c0 = gtid << 2;              // element index in first half
    const int col = c0 & (IM - 1);         // column (same for both halves)

    const float* pa = in + c0;
    const float* pb = in + c0 + HALF;

    float ga[20], gb[20];
    // Warp spans 128 aligned columns; only wbase==384 warps can reach the pad.
    if (col < 384) {
        #pragma unroll
        for (int i = 0; i < 5; ++i) {
            float4 va = *reinterpret_cast<const float4*>(pa + 4 * i);
            float4 vb = *reinterpret_cast<const float4*>(pb + 4 * i);
            ga[4*i+0] = va.x - 0.1f * (4*i+0);
            ga[4*i+1] = va.y - 0.1f * (4*i+1);
            ga[4*i+2] = va.z - 0.1f * (4*i+2);
            ga[4*i+3] = va.w - 0.1f * (4*i+3);
            gb[4*i+0] = vb.x - 0.1f * (4*i+0);
            gb[4*i+1] = vb.y - 0.1f * (4*i+1);
            gb[4*i+2] = vb.z - 0.1f * (4*i+2);
            gb[4*i+3] = vb.w - 0.1f * (4*i+3);
        }
    } else {
        float4 va0 = *reinterpret_cast<const float4*>(pa);
        float4 vb0 = *reinterpret_cast<const float4*>(pb);
        ga[0] = va0.x; ga[1] = va0.y - 0.1f; ga[2] = va0.z - 0.2f; ga[3] = va0.w - 0.3f;
        gb[0] = vb0.x; gb[1] = vb0.y - 0.1f; gb[2] = vb0.z - 0.2f; gb[3] = vb0.w - 0.3f;
        #pragma unroll
        for (int i = 1; i < 5; ++i) {
            if (col + 4 * i <= IM - 4) {
                float4 va = *reinterpret_cast<const float4*>(pa + 4 * i);
                float4 vb = *reinterpret_cast<const float4*>(pb + 4 * i);
                ga[4*i+0] = va.x - 0.1f * (4*i+0);
                ga[4*i+1] = va.y - 0.1f * (4*i+1);
                ga[4*i+2] = va.z - 0.1f * (4*i+2);
                ga[4*i+3] = va.w - 0.1f * (4*i+3);
                gb[4*i+0] = vb.x - 0.1f * (4*i+0);
                gb[4*i+1] = vb.y - 0.1f * (4*i+1);
                gb[4*i+2] = vb.z - 0.1f * (4*i+2);
                gb[4*i+3] = vb.w - 0.1f * (4*i+3);
            } else {                       // beyond row end: never wins
                ga[4*i+0] = NEG; ga[4*i+1] = NEG; ga[4*i+2] = NEG; ga[4*i+3] = NEG;
                gb[4*i+0] = NEG; gb[4*i+1] = NEG; gb[4*i+2] = NEG; gb[4*i+3] = NEG;
            }
        }
    }

    #pragma unroll
    for (int h = 0; h < 2; ++h) {
        const float* g = (h == 0) ? ga : gb;
        // balanced-tree max over g[4..16]
        const float t45   = fmaxf(g[4],  g[5]);
        const float t67   = fmaxf(g[6],  g[7]);
        const float t89   = fmaxf(g[8],  g[9]);
        const float t1011 = fmaxf(g[10], g[11]);
        const float t1213 = fmaxf(g[12], g[13]);
        const float t1415 = fmaxf(g[14], g[15]);
        const float q0 = fmaxf(t45,  t67);
        const float q1 = fmaxf(t89,  t1011);
        const float q2 = fmaxf(t1213, t1415);
        const float cm = fmaxf(fmaxf(q0, q1), fmaxf(q2, g[16]));

        const float a = fmaxf(g[2], g[3]);
        const float b = fmaxf(g[17], g[18]);
        const float m0 = fmaxf(cm, fmaxf(g[1], a));
        const float m1 = fmaxf(cm, fmaxf(a, g[17]));
        const float m2 = fmaxf(cm, fmaxf(g[3], b));
        const float m3 = fmaxf(cm, fmaxf(b, g[19]));

        float4 o;
        o.x = __saturatef(1.0f + (g[0] - m0));
        o.y = __saturatef(1.0f + (g[1] - m1));
        o.z = __saturatef(1.0f + (g[2] - m2));
        o.w = __saturatef(1.0f + (g[3] - m3));

        __stcs(reinterpret_cast<float4*>(out + c0 + h * HALF), o);
    }
}

extern "C" void kernel_launch(void* const* d_in, const int* in_sizes, int n_in,
                              void* d_out, int out_size) {
    const float* in = (const float*)d_in[0];
    float* out = (float*)d_out;
    const int threads_total = HALF / 4;        // 524,288 threads
    shadow_dual<<<threads_total / THREADS, THREADS>>>(in, out);
}